// round 3
// baseline (speedup 1.0000x reference)
#include <cuda_runtime.h>
#include <cstdint>

#define N_IN    50000
#define C_DIM   64
#define T_DIM   8
#define E_EDGES 800000
#define N_OUT   50000
#define F_DIM   64
#define KDIM    512   // T*C

// ---------------- scratch (device globals; no allocation allowed) ----------------
__device__ int   g_idx64;               // 1 if indices are int64, 0 if int32
__device__ int   g_counts[N_OUT];
__device__ int   g_offsets[N_OUT + 1];
__device__ int   g_cursor[N_OUT];
__device__ int   g_perm[E_EDGES];
__device__ float g_agg[(size_t)N_OUT * KDIM];   // 102.4 MB

// ---------------- index accessors (dtype-robust) ----------------
__device__ __forceinline__ int idx_out_of(const int* __restrict__ idx, int e, int is64) {
    // int32 layout: [out0,in0,out1,in1,...]; int64 little-endian: [out0,0,in0,0,...]
    return is64 ? idx[4 * e] : idx[2 * e];
}
__device__ __forceinline__ int idx_in_of(const int* __restrict__ idx, int e, int is64) {
    return is64 ? idx[4 * e + 2] : idx[2 * e + 1];
}

// ---------------- K-1: probe index dtype ----------------
// int64 values < 2^31 => every odd int32 word is 0. int32 data: odd words are
// random indices in [0, 50000) — all-zero over 128 samples is impossible here.
__global__ void probe_kernel(const int* __restrict__ idx) {
    if (threadIdx.x == 0) {
        int nz = 0;
        for (int i = 1; i < 256; i += 2) nz |= idx[i];
        g_idx64 = (nz == 0) ? 1 : 0;
    }
}

// ---------------- K0: zero histogram ----------------
__global__ void zero_counts_kernel() {
    int i = blockIdx.x * blockDim.x + threadIdx.x;
    if (i < N_OUT) g_counts[i] = 0;
}

// ---------------- K1: histogram of idx_out ----------------
__global__ void hist_kernel(const int* __restrict__ idx) {
    int e = blockIdx.x * blockDim.x + threadIdx.x;
    if (e < E_EDGES) {
        int o = idx_out_of(idx, e, g_idx64);
        atomicAdd(&g_counts[o], 1);
    }
}

// ---------------- K2: single-block exclusive scan over 50000 counts ----------------
__global__ __launch_bounds__(1024) void scan_kernel() {
    __shared__ int warp_sums[32];
    __shared__ int s_running;
    const int tid = threadIdx.x;
    if (tid == 0) s_running = 0;
    __syncthreads();

    for (int base = 0; base < N_OUT; base += 1024) {
        int i = base + tid;
        int v = (i < N_OUT) ? g_counts[i] : 0;

        // warp inclusive scan
        int x = v;
        #pragma unroll
        for (int d = 1; d < 32; d <<= 1) {
            int y = __shfl_up_sync(0xffffffffu, x, d);
            if ((tid & 31) >= d) x += y;
        }
        if ((tid & 31) == 31) warp_sums[tid >> 5] = x;
        __syncthreads();
        if (tid < 32) {
            int s = warp_sums[tid];
            #pragma unroll
            for (int d = 1; d < 32; d <<= 1) {
                int y = __shfl_up_sync(0xffffffffu, s, d);
                if (tid >= d) s += y;
            }
            warp_sums[tid] = s;  // inclusive warp totals
        }
        __syncthreads();
        int warp_prefix = (tid >= 32) ? warp_sums[(tid >> 5) - 1] : 0;
        int incl = warp_prefix + x;
        int excl = incl - v;
        int run  = s_running;
        if (i < N_OUT) {
            g_offsets[i] = run + excl;
            g_cursor[i]  = run + excl;
        }
        __syncthreads();
        if (tid == 1023) s_running = run + incl;
        __syncthreads();
    }
    if (tid == 0) g_offsets[N_OUT] = s_running;
}

// ---------------- K3: scatter edge ids into CSR slots ----------------
__global__ void fill_perm_kernel(const int* __restrict__ idx) {
    int e = blockIdx.x * blockDim.x + threadIdx.x;
    if (e < E_EDGES) {
        int o = idx_out_of(idx, e, g_idx64);
        int p = atomicAdd(&g_cursor[o], 1);
        g_perm[p] = e;
    }
}

// ---------------- K4: pull phase — one warp per output node ----------------
// Each lane owns channels c = 2*lane, 2*lane+1; acc[t] kept in registers.
__global__ __launch_bounds__(256) void pull_kernel(
    const float* __restrict__ node,
    const float* __restrict__ edgef,
    const int* __restrict__ idx)
{
    int w = blockIdx.x * 8 + (threadIdx.x >> 5);   // output node (grid sized exactly)
    int lane = threadIdx.x & 31;
    int is64 = g_idx64;
    int s    = g_offsets[w];
    int send = g_offsets[w + 1];

    float accx[T_DIM], accy[T_DIM];
    #pragma unroll
    for (int t = 0; t < T_DIM; t++) { accx[t] = 0.f; accy[t] = 0.f; }

    for (int p = s; p < send; p++) {
        int e = g_perm[p];                          // broadcast load
        float wv = 0.f;
        if (lane < 8) wv = edgef[lane * E_EDGES + e];
        int nin = idx_in_of(idx, e, is64);          // broadcast load
        float2 nv = *(const float2*)(node + (size_t)nin * 64 + lane * 2);
        #pragma unroll
        for (int t = 0; t < T_DIM; t++) {
            float wt = __shfl_sync(0xffffffffu, wv, t);
            accx[t] += wt * nv.x;
            accy[t] += wt * nv.y;
        }
    }

    size_t base = (size_t)w * KDIM + lane * 2;
    #pragma unroll
    for (int t = 0; t < T_DIM; t++) {
        *(float2*)&g_agg[base + t * 64] = make_float2(accx[t], accy[t]);
    }
}

// ---------------- K5: out = agg(50000x512) @ W(512x64) + bias ----------------
#define BM 128
#define BN 64
#define BK 16
#define TM 8
#define TN 4

__global__ __launch_bounds__(256) void gemm_kernel(
    const float* __restrict__ W,      // kernel tensor, (T*C, F) row-major
    const float* __restrict__ bias,
    float* __restrict__ out)
{
    __shared__ float As[BK][BM];
    __shared__ float Bs[BK][BN];

    const int tid  = threadIdx.x;
    const int row0 = blockIdx.x * BM;
    const int tx   = tid % 16;   // column group: cols tx*4 .. tx*4+3
    const int ty   = tid / 16;   // row group:    rows ty*8 .. ty*8+7

    float acc[TM][TN];
    #pragma unroll
    for (int i = 0; i < TM; i++)
        #pragma unroll
        for (int j = 0; j < TN; j++) acc[i][j] = 0.f;

    for (int k0 = 0; k0 < KDIM; k0 += BK) {
        // Load A tile: 128x16 floats = 512 float4, 2 per thread, store transposed
        #pragma unroll
        for (int i = 0; i < 2; i++) {
            int idx4 = tid * 2 + i;       // 0..511
            int r   = idx4 >> 2;          // 0..127
            int c4  = idx4 & 3;           // 0..3
            int gr  = row0 + r;
            float4 v = make_float4(0.f, 0.f, 0.f, 0.f);
            if (gr < N_OUT)
                v = *(const float4*)&g_agg[(size_t)gr * KDIM + k0 + c4 * 4];
            As[c4 * 4 + 0][r] = v.x;
            As[c4 * 4 + 1][r] = v.y;
            As[c4 * 4 + 2][r] = v.z;
            As[c4 * 4 + 3][r] = v.w;
        }
        // Load B tile: 16x64 floats = 256 float4, 1 per thread
        {
            int kr = tid >> 4;   // 0..15
            int c4 = tid & 15;   // 0..15
            float4 v = *(const float4*)&W[(size_t)(k0 + kr) * 64 + c4 * 4];
            *(float4*)&Bs[kr][c4 * 4] = v;
        }
        __syncthreads();

        #pragma unroll
        for (int kk = 0; kk < BK; kk++) {
            float a[TM], b[TN];
            #pragma unroll
            for (int i = 0; i < TM; i++) a[i] = As[kk][ty * TM + i];
            #pragma unroll
            for (int j = 0; j < TN; j++) b[j] = Bs[kk][tx * TN + j];
            #pragma unroll
            for (int i = 0; i < TM; i++)
                #pragma unroll
                for (int j = 0; j < TN; j++)
                    acc[i][j] += a[i] * b[j];
        }
        __syncthreads();
    }

    float4 bv = *(const float4*)&bias[tx * TN];
    #pragma unroll
    for (int i = 0; i < TM; i++) {
        int gr = row0 + ty * TM + i;
        if (gr < N_OUT) {
            float4 o;
            o.x = acc[i][0] + bv.x;
            o.y = acc[i][1] + bv.y;
            o.z = acc[i][2] + bv.z;
            o.w = acc[i][3] + bv.w;
            *(float4*)&out[(size_t)gr * F_DIM + tx * TN] = o;
        }
    }
}

// ---------------- launch ----------------
extern "C" void kernel_launch(void* const* d_in, const int* in_sizes, int n_in,
                              void* d_out, int out_size)
{
    const float* node  = nullptr;
    const float* edgef = nullptr;
    const int*   idx   = nullptr;
    const float* W     = nullptr;
    const float* bias  = nullptr;

    // Map inputs by unique element counts (robust to scalar 'out_size' presence)
    for (int i = 0; i < n_in; i++) {
        switch (in_sizes[i]) {
            case N_IN * C_DIM:          node  = (const float*)d_in[i]; break; // 3,200,000
            case T_DIM * E_EDGES:       edgef = (const float*)d_in[i]; break; // 6,400,000
            case E_EDGES * 2:           idx   = (const int*)d_in[i];   break; // 1,600,000
            case T_DIM * C_DIM * F_DIM: W     = (const float*)d_in[i]; break; // 32,768
            case F_DIM:                 bias  = (const float*)d_in[i]; break; // 64
            default: break;
        }
    }
    float* out = (float*)d_out;

    probe_kernel<<<1, 32>>>(idx);
    zero_counts_kernel<<<(N_OUT + 255) / 256, 256>>>();
    hist_kernel<<<(E_EDGES + 255) / 256, 256>>>(idx);
    scan_kernel<<<1, 1024>>>();
    fill_perm_kernel<<<(E_EDGES + 255) / 256, 256>>>(idx);
    pull_kernel<<<N_OUT / 8, 256>>>(node, edgef, idx);
    gemm_kernel<<<(N_OUT + BM - 1) / BM, 256>>>(W, bias, out);
}